// round 11
// baseline (speedup 1.0000x reference)
#include <cuda_runtime.h>
#include <cstdint>

// Problem constants
#define BB 64
#define SS 512
#define HH 768
#define EE 128
#define TT_ 4
#define NT 5
#define H4 192      // H/4 float4 lanes
#define GRID 1184   // 148 SMs x 8 blocks: exactly one co-resident wave
#define TPB (SS + EE)   // 640 tasks per batch

// Scratch (no allocs allowed). Packed per-(b,s) coefficients:
//   .x = 5 x 6-bit type counts, .y = float conf-sum (as bits)
__device__ uint2 g_coef[BB * SS];
__device__ int g_ready[BB];   // per-batch publish flags (self-resetting)
__device__ int g_all;         // all builds done
__device__ int g_bcnt;        // builders finished
__device__ int g_done;        // blocks finished (for reset)

__device__ __forceinline__ int ld_acquire(const int* p) {
    int v;
    asm volatile("ld.acquire.gpu.b32 %0, [%1];" : "=r"(v) : "l"(p) : "memory");
    return v;
}
__device__ __forceinline__ void st_release(int* p, int v) {
    asm volatile("st.release.gpu.b32 [%0], %1;" :: "l"(p), "r"(v) : "memory");
}

// ---------------------------------------------------------------------------
// Single kernel, one co-resident wave, per-batch flags (no global barrier).
// Blocks 0..63 build batch-b packed coef tables and publish g_ready[b];
// the last builder sets g_all. Main loop (R9 structure) checks readiness
// only on batch transition, and never again once g_all is observed.
// Flags self-reset at kernel end (no memset node).
// ---------------------------------------------------------------------------
__global__ void __launch_bounds__(H4, 8) fused_kernel(
    const float* __restrict__ hidden,       // [B,S,H]
    const int* __restrict__ types,          // [B,E]
    const float* __restrict__ conf,         // [B,E]
    const int* __restrict__ ent_tokens,     // [E,T]
    const float* __restrict__ type_table,   // [NT,H]
    const float* __restrict__ conf_w,       // [H]
    const float* __restrict__ conf_b,       // [H]
    float* __restrict__ out_enh,            // [B,S,H]
    float* __restrict__ out_emb) {          // [B,E,H]
    __shared__ float4 s_tab[NT + 1][H4];    // [0..4]=type_table+conf_b, [5]=conf_w
    __shared__ unsigned s_cnt[SS];
    __shared__ float s_conf[SS];
    __shared__ int s_st;
    int tid = threadIdx.x;                  // 0..191
    int h = tid * 4;

    // table prologue — each thread only ever reads its own lane, no sync needed
    {
        float4 cb4 = *reinterpret_cast<const float4*>(conf_b + h);
        s_tab[NT][tid] = *reinterpret_cast<const float4*>(conf_w + h);
#pragma unroll
        for (int ty = 0; ty < NT; ty++) {
            float4 v = *reinterpret_cast<const float4*>(type_table + ty * HH + h);
            s_tab[ty][tid] = make_float4(v.x + cb4.x, v.y + cb4.y, v.z + cb4.z, v.w + cb4.w);
        }
    }

    // ---- build phase: blocks 0..63 build their batch's coef table ----
    if (blockIdx.x < BB) {
        int b = blockIdx.x;
        for (int i = tid; i < SS; i += H4) { s_cnt[i] = 0u; s_conf[i] = 0.f; }
        __syncthreads();
        for (int p = tid; p < EE * TT_; p += H4) {
            int tok = __ldg(&ent_tokens[p]);
            int e = p >> 2;
            int ty = __ldg(&types[b * EE + e]);
            float c = __ldg(&conf[b * EE + e]);
            atomicAdd(&s_cnt[tok], 1u << (6 * ty));
            atomicAdd(&s_conf[tok], c);
        }
        __syncthreads();
        for (int i = tid; i < SS; i += H4)
            g_coef[b * SS + i] = make_uint2(s_cnt[i], __float_as_uint(s_conf[i]));
        __syncthreads();
        if (tid == 0) {
            __threadfence();                 // coef writes before flag
            st_release(&g_ready[b], 1);
            int n = atomicAdd(&g_bcnt, 1);
            if (n == BB - 1) st_release(&g_all, 1);
        }
    }

    // ---- main loop (R9 body) with lazy per-batch readiness checks ----
    int idx = blockIdx.x;
    int b = (idx >= TPB) ? 1 : 0;
    int r = idx - b * TPB;
    int last_ready = -1;
    bool all_ready = false;

    while (b < BB) {
        if (!all_ready && b > last_ready) {
            if (tid == 0) {
                int a = ld_acquire(&g_all);
                if (!a) {
                    while (ld_acquire(&g_ready[b]) == 0) __nanosleep(32);
                }
                s_st = a;
            }
            __syncthreads();
            all_ready = (s_st != 0);
            last_ready = b;
            __syncthreads();                 // protect s_st before next write
        }

        const float* hb = hidden + (size_t)b * SS * HH;
        if (r < SS) {
            // enhance row (b, s=r)
            int s = r;
            uint2 cc = g_coef[b * SS + s];
            float4 v = *reinterpret_cast<const float4*>(hb + (size_t)s * HH + h);
            unsigned cnt = cc.x;
            if (cnt) {                       // uniform: row has entities
#pragma unroll
                for (int q = 0; q < NT; q++) {
                    unsigned a = (cnt >> (6 * q)) & 63u;
                    if (a) {                 // uniform
                        float fa = (float)a;
                        float4 t = s_tab[q][tid];
                        v.x += fa * t.x; v.y += fa * t.y;
                        v.z += fa * t.z; v.w += fa * t.w;
                    }
                }
                float cs = __uint_as_float(cc.y);
                float4 t = s_tab[NT][tid];
                v.x += cs * t.x; v.y += cs * t.y; v.z += cs * t.z; v.w += cs * t.w;
            }
            __stcs(reinterpret_cast<float4*>(
                out_enh + ((size_t)b * SS + s) * HH + h), v);
        } else {
            // entity embedding (b, e): 0.25 * sum_t enhanced[b, tok, :]
            int e = r - SS;
            float4 acc = make_float4(0.f, 0.f, 0.f, 0.f);
            float a0 = 0.f, a1 = 0.f, a2 = 0.f, a3 = 0.f, a4 = 0.f, ac = 0.f;
#pragma unroll
            for (int t = 0; t < TT_; t++) {
                int s = __ldg(&ent_tokens[e * TT_ + t]);
                uint2 cc = g_coef[b * SS + s];
                unsigned cnt = cc.x;
                a0 += (float)(cnt & 63u);
                a1 += (float)((cnt >> 6) & 63u);
                a2 += (float)((cnt >> 12) & 63u);
                a3 += (float)((cnt >> 18) & 63u);
                a4 += (float)((cnt >> 24) & 63u);
                ac += __uint_as_float(cc.y);
                float4 v = *reinterpret_cast<const float4*>(hb + (size_t)s * HH + h);
                acc.x += v.x; acc.y += v.y; acc.z += v.z; acc.w += v.w;
            }
            float4 t;
            t = s_tab[0][tid]; acc.x += a0 * t.x; acc.y += a0 * t.y; acc.z += a0 * t.z; acc.w += a0 * t.w;
            t = s_tab[1][tid]; acc.x += a1 * t.x; acc.y += a1 * t.y; acc.z += a1 * t.z; acc.w += a1 * t.w;
            t = s_tab[2][tid]; acc.x += a2 * t.x; acc.y += a2 * t.y; acc.z += a2 * t.z; acc.w += a2 * t.w;
            t = s_tab[3][tid]; acc.x += a3 * t.x; acc.y += a3 * t.y; acc.z += a3 * t.z; acc.w += a3 * t.w;
            t = s_tab[4][tid]; acc.x += a4 * t.x; acc.y += a4 * t.y; acc.z += a4 * t.z; acc.w += a4 * t.w;
            t = s_tab[5][tid]; acc.x += ac * t.x; acc.y += ac * t.y; acc.z += ac * t.z; acc.w += ac * t.w;
            acc.x *= 0.25f; acc.y *= 0.25f; acc.z *= 0.25f; acc.w *= 0.25f;
            __stcs(reinterpret_cast<float4*>(
                out_emb + ((size_t)b * EE + e) * HH + h), acc);
        }

        // advance: idx += GRID == +1 batch +544 tasks (no division)
        b += 1;
        r += GRID - TPB;                     // +544
        if (r >= TPB) { r -= TPB; b += 1; }
    }

    // ---- self-reset of sync state (last block) ----
    __syncthreads();
    if (tid == 0) {
        __threadfence();
        int d = atomicAdd(&g_done, 1);
        if (d == GRID - 1) {
            for (int i = 0; i < BB; i++) g_ready[i] = 0;
            g_all = 0;
            g_bcnt = 0;
            __threadfence();
            g_done = 0;
        }
    }
}

// ---------------------------------------------------------------------------
// Inputs in metadata order:
// 0 hidden_states (B,S,H) f32 | 1 entity_types (B,E) i32 | 2 entity_confidences (B,E) f32
// 3 ent_tokens (E,T) i32 | 4 type_table (NT,H) f32 | 5 conf_w (1,H) f32 | 6 conf_b (H) f32
// Output: enhanced (B,S,H) then entity_embeddings (B,E,H), concatenated.
// ---------------------------------------------------------------------------
extern "C" void kernel_launch(void* const* d_in, const int* in_sizes, int n_in,
                              void* d_out, int out_size) {
    const float* hidden   = (const float*)d_in[0];
    const int*   types    = (const int*)d_in[1];
    const float* conf     = (const float*)d_in[2];
    const int*   ent_tok  = (const int*)d_in[3];
    const float* ttab     = (const float*)d_in[4];
    const float* conf_w   = (const float*)d_in[5];
    const float* conf_b   = (const float*)d_in[6];

    float* out_enh = (float*)d_out;
    float* out_emb = out_enh + (size_t)BB * SS * HH;

    fused_kernel<<<GRID, H4>>>(hidden, types, conf, ent_tok, ttab,
                               conf_w, conf_b, out_enh, out_emb);
}

// round 12
// speedup vs baseline: 1.1357x; 1.1357x over previous
#include <cuda_runtime.h>
#include <cstdint>

// Problem constants
#define BB 64
#define SS 512
#define HH 768
#define EE 128
#define TT_ 4
#define NT 5
#define H4 192      // H/4 float4 lanes
#define GRID 1184   // 148 SMs x 8 blocks
#define TPB (SS + EE)   // 640 tasks per batch

// Scratch (no allocs allowed). Packed per-(b,s) coefficients:
//   .x = 5 x 6-bit type counts, .y = float conf-sum (as bits)
__device__ uint2 g_coef[BB * SS];

// ---------------------------------------------------------------------------
// P: per-batch coefficient build. One block per batch b (512 threads, one per
// flat (e,t)). Packed histogram in smem, 8-byte store per row.
// ---------------------------------------------------------------------------
__global__ void __launch_bounds__(512) rowcoef_kernel(
    const int* __restrict__ ent_tokens,     // [E,T]
    const int* __restrict__ types,          // [B,E]
    const float* __restrict__ conf) {       // [B,E]
    __shared__ unsigned s_cnt[SS];
    __shared__ float s_conf[SS];
    int b = blockIdx.x;
    int tid = threadIdx.x;                  // 0..511 == flat (e,t)

    s_cnt[tid] = 0u;
    s_conf[tid] = 0.f;
    __syncthreads();

    int tok = ent_tokens[tid];
    int e = tid >> 2;
    int ty = types[b * EE + e];
    float c = conf[b * EE + e];
    atomicAdd(&s_cnt[tok], 1u << (6 * ty));
    atomicAdd(&s_conf[tok], c);
    __syncthreads();

    g_coef[b * SS + tid] = make_uint2(s_cnt[tid], __float_as_uint(s_conf[tid]));
}

// ---------------------------------------------------------------------------
// Fused main kernel: R9 structure (persistent grid-stride, smem tables,
// uniform-sparsity combine, 8B packed coef loads) plus:
//   - divisionless task advance (incremental b/r bookkeeping)
//   - __stcs streaming stores on both outputs (keep L2 for gathered rows)
// ---------------------------------------------------------------------------
__global__ void __launch_bounds__(H4, 8) fused_kernel(
    const float* __restrict__ hidden,       // [B,S,H]
    const int* __restrict__ ent_tokens,     // [E,T]
    const float* __restrict__ type_table,   // [NT,H]
    const float* __restrict__ conf_w,       // [H]
    const float* __restrict__ conf_b,       // [H]
    float* __restrict__ out_enh,            // [B,S,H]
    float* __restrict__ out_emb) {          // [B,E,H]
    __shared__ float4 s_tab[NT + 1][H4];    // [0..4]=type_table+conf_b, [5]=conf_w
    int tid = threadIdx.x;                  // 0..191
    int h = tid * 4;

    {
        float4 cb4 = *reinterpret_cast<const float4*>(conf_b + h);
        s_tab[NT][tid] = *reinterpret_cast<const float4*>(conf_w + h);
#pragma unroll
        for (int ty = 0; ty < NT; ty++) {
            float4 v = *reinterpret_cast<const float4*>(type_table + ty * HH + h);
            s_tab[ty][tid] = make_float4(v.x + cb4.x, v.y + cb4.y, v.z + cb4.z, v.w + cb4.w);
        }
    }
    __syncthreads();

    // divisionless task walk: start at blockIdx.x (GRID=1184 < 2*TPB)
    int b = (blockIdx.x >= TPB) ? 1 : 0;
    int r = blockIdx.x - b * TPB;

    while (b < BB) {
        const float* hb = hidden + (size_t)b * SS * HH;

        if (r < SS) {
            // ---- enhance row (b, s=r) ----
            int s = r;
            uint2 cc = __ldg(&g_coef[b * SS + s]);
            float4 v = *reinterpret_cast<const float4*>(hb + (size_t)s * HH + h);
            unsigned cnt = cc.x;
            if (cnt) {                       // uniform: row has entities
#pragma unroll
                for (int q = 0; q < NT; q++) {
                    unsigned a = (cnt >> (6 * q)) & 63u;
                    if (a) {                 // uniform
                        float fa = (float)a;
                        float4 t = s_tab[q][tid];
                        v.x += fa * t.x; v.y += fa * t.y;
                        v.z += fa * t.z; v.w += fa * t.w;
                    }
                }
                float cs = __uint_as_float(cc.y);
                float4 t = s_tab[NT][tid];
                v.x += cs * t.x; v.y += cs * t.y; v.z += cs * t.z; v.w += cs * t.w;
            }
            __stcs(reinterpret_cast<float4*>(
                out_enh + ((size_t)b * SS + s) * HH + h), v);
        } else {
            // ---- entity embedding (b, e): 0.25 * sum_t enhanced[b, tok, :] ----
            int e = r - SS;
            float4 acc = make_float4(0.f, 0.f, 0.f, 0.f);
            float a0 = 0.f, a1 = 0.f, a2 = 0.f, a3 = 0.f, a4 = 0.f, ac = 0.f;
#pragma unroll
            for (int t = 0; t < TT_; t++) {
                int s = __ldg(&ent_tokens[e * TT_ + t]);
                uint2 cc = __ldg(&g_coef[b * SS + s]);
                unsigned cnt = cc.x;
                a0 += (float)(cnt & 63u);
                a1 += (float)((cnt >> 6) & 63u);
                a2 += (float)((cnt >> 12) & 63u);
                a3 += (float)((cnt >> 18) & 63u);
                a4 += (float)((cnt >> 24) & 63u);
                ac += __uint_as_float(cc.y);
                float4 v = *reinterpret_cast<const float4*>(hb + (size_t)s * HH + h);
                acc.x += v.x; acc.y += v.y; acc.z += v.z; acc.w += v.w;
            }
            float4 t;
            t = s_tab[0][tid]; acc.x += a0 * t.x; acc.y += a0 * t.y; acc.z += a0 * t.z; acc.w += a0 * t.w;
            t = s_tab[1][tid]; acc.x += a1 * t.x; acc.y += a1 * t.y; acc.z += a1 * t.z; acc.w += a1 * t.w;
            t = s_tab[2][tid]; acc.x += a2 * t.x; acc.y += a2 * t.y; acc.z += a2 * t.z; acc.w += a2 * t.w;
            t = s_tab[3][tid]; acc.x += a3 * t.x; acc.y += a3 * t.y; acc.z += a3 * t.z; acc.w += a3 * t.w;
            t = s_tab[4][tid]; acc.x += a4 * t.x; acc.y += a4 * t.y; acc.z += a4 * t.z; acc.w += a4 * t.w;
            t = s_tab[5][tid]; acc.x += ac * t.x; acc.y += ac * t.y; acc.z += ac * t.z; acc.w += ac * t.w;
            acc.x *= 0.25f; acc.y *= 0.25f; acc.z *= 0.25f; acc.w *= 0.25f;
            __stcs(reinterpret_cast<float4*>(
                out_emb + ((size_t)b * EE + e) * HH + h), acc);
        }

        // advance by GRID tasks: +1 batch +544 tasks, wrap once if needed
        b += 1;
        r += GRID - TPB;                     // +544
        if (r >= TPB) { r -= TPB; b += 1; }
    }
}

// ---------------------------------------------------------------------------
// Inputs in metadata order:
// 0 hidden_states (B,S,H) f32 | 1 entity_types (B,E) i32 | 2 entity_confidences (B,E) f32
// 3 ent_tokens (E,T) i32 | 4 type_table (NT,H) f32 | 5 conf_w (1,H) f32 | 6 conf_b (H) f32
// Output: enhanced (B,S,H) then entity_embeddings (B,E,H), concatenated.
// ---------------------------------------------------------------------------
extern "C" void kernel_launch(void* const* d_in, const int* in_sizes, int n_in,
                              void* d_out, int out_size) {
    const float* hidden   = (const float*)d_in[0];
    const int*   types    = (const int*)d_in[1];
    const float* conf     = (const float*)d_in[2];
    const int*   ent_tok  = (const int*)d_in[3];
    const float* ttab     = (const float*)d_in[4];
    const float* conf_w   = (const float*)d_in[5];
    const float* conf_b   = (const float*)d_in[6];

    float* out_enh = (float*)d_out;
    float* out_emb = out_enh + (size_t)BB * SS * HH;

    rowcoef_kernel<<<BB, 512>>>(ent_tok, types, conf);
    fused_kernel<<<GRID, H4>>>(hidden, ent_tok, ttab, conf_w, conf_b,
                               out_enh, out_emb);
}